// round 1
// baseline (speedup 1.0000x reference)
#include <cuda_runtime.h>
#include <math.h>

#define NMAX 20000
#define KNN 6

// ---------------- scratch (device globals; no allocation allowed) ----------------
__device__ __align__(16) float g_cnt [NMAX];
__device__ __align__(16) float g_agg1[NMAX*16];
__device__ __align__(16) float g_x1  [NMAX*16];
__device__ __align__(16) float g_sq1 [NMAX];
__device__ __align__(16) int   g_idx1[NMAX*KNN];
__device__ __align__(16) float g_y1  [NMAX*32];
__device__ __align__(16) float g_sq2 [NMAX];
__device__ __align__(16) float g_cat0[NMAX*48];
__device__ __align__(16) float g_agg2[NMAX*48];
__device__ __align__(16) int   g_idx2[NMAX*KNN];
__device__ __align__(16) float g_x3  [NMAX*64];
__device__ __align__(16) float g_y2  [NMAX*32];
__device__ __align__(16) float g_h1  [NMAX*96];

// ---------------- init: agg1 = x (self loop), cnt = 1 ----------------
__global__ void init1_kernel(const float* __restrict__ x, int n){
    int t = blockIdx.x*blockDim.x + threadIdx.x;
    if (t < n*16) g_agg1[t] = x[t];
    if (t < n)    g_cnt[t]  = 1.0f;
}

// ---------------- scatter-add of x[src] into agg1[dst], count edges ----------------
__global__ void scatter1_kernel(const int* __restrict__ src, const int* __restrict__ dst,
                                const float* __restrict__ x, int E){
    int t = blockIdx.x*blockDim.x + threadIdx.x;
    int e = t >> 2;
    if (e >= E) return;
    int q = t & 3;
    int s = src[e], d = dst[e];
    if (q == 0) atomicAdd(&g_cnt[d], 1.0f);
    float4 v = reinterpret_cast<const float4*>(x)[s*4 + q];
    float* a = &g_agg1[d*16 + q*4];
    atomicAdd(a+0, v.x); atomicAdd(a+1, v.y); atomicAdd(a+2, v.z); atomicAdd(a+3, v.w);
}

// ---------------- feast output: out = relu((agg/cnt) @ W + b), optional ||row||^2 ----------------
template<int IN, int OUT, bool WSQ>
__global__ void feast_kernel(const float* __restrict__ agg, const float* __restrict__ W,
                             const float* __restrict__ b, int n,
                             float* __restrict__ out, float* __restrict__ sqout){
    __shared__ float sW[IN*OUT];
    __shared__ float sb[OUT];
    for (int t = threadIdx.x; t < IN*OUT; t += blockDim.x) sW[t] = W[t];
    for (int t = threadIdx.x; t < OUT;    t += blockDim.x) sb[t] = b[t];
    __syncthreads();
    int i = blockIdx.x*blockDim.x + threadIdx.x;
    if (i >= n) return;
    float inv = 1.0f / g_cnt[i];
    float acc[OUT];
#pragma unroll
    for (int c = 0; c < OUT; c++) acc[c] = sb[c];
    for (int d = 0; d < IN; d++){
        float v = agg[i*IN+d] * inv;
#pragma unroll
        for (int c = 0; c < OUT; c++) acc[c] = fmaf(v, sW[d*OUT+c], acc[c]);
    }
    float sq = 0.f;
#pragma unroll
    for (int c = 0; c < OUT; c++){
        float r = fmaxf(acc[c], 0.f);
        out[i*OUT+c] = r;
        sq = fmaf(r, r, sq);
    }
    if (WSQ) sqout[i] = sq;
}

// ---------------- streaming top-6 insertion (ascending-j scan => lower index wins ties) ----------------
__device__ __forceinline__ void upd6(float d, int j, float bd[KNN], int bi[KNN]){
    if (d < bd[KNN-1]){
        bd[KNN-1] = d; bi[KNN-1] = j;
#pragma unroll
        for (int k = KNN-1; k > 0; k--){
            if (bd[k] < bd[k-1]){
                float td = bd[k]; bd[k] = bd[k-1]; bd[k-1] = td;
                int   ti = bi[k]; bi[k] = bi[k-1]; bi[k-1] = ti;
            }
        }
    }
}

// ---------------- fused pairwise-distance + top-6 kNN ----------------
template<int DIM>
__global__ void knn_kernel(const float* __restrict__ X, const float* __restrict__ sq,
                           int n, int* __restrict__ outidx){
    const int TS = 128;
    const int Q  = DIM/4;
    __shared__ float4 xs[TS*Q];
    __shared__ float  sqs[TS];
    int i = blockIdx.x*blockDim.x + threadIdx.x;
    float xi[DIM];
    if (i < n){
#pragma unroll
        for (int d = 0; d < DIM; d++) xi[d] = X[i*DIM+d];
    }
    float bd[KNN]; int bi[KNN];
#pragma unroll
    for (int k = 0; k < KNN; k++){ bd[k] = INFINITY; bi[k] = -1; }

    for (int jt = 0; jt < n; jt += TS){
        int tile = min(TS, n - jt);
        __syncthreads();
        for (int t = threadIdx.x; t < tile*Q; t += blockDim.x)
            xs[t] = reinterpret_cast<const float4*>(X)[jt*Q + t];
        for (int t = threadIdx.x; t < tile; t += blockDim.x)
            sqs[t] = sq[jt + t];
        __syncthreads();
        if (i >= n) continue;

        int jj = 0;
        for (; jj + 4 <= tile; jj += 4){
            float d0=0.f, d1=0.f, d2=0.f, d3=0.f;
#pragma unroll
            for (int q = 0; q < Q; q++){
                float4 a0 = xs[(jj+0)*Q+q];
                float4 a1 = xs[(jj+1)*Q+q];
                float4 a2 = xs[(jj+2)*Q+q];
                float4 a3 = xs[(jj+3)*Q+q];
                float w0 = xi[4*q+0], w1 = xi[4*q+1], w2 = xi[4*q+2], w3 = xi[4*q+3];
                d0 = fmaf(w0, a0.x, d0); d0 = fmaf(w1, a0.y, d0); d0 = fmaf(w2, a0.z, d0); d0 = fmaf(w3, a0.w, d0);
                d1 = fmaf(w0, a1.x, d1); d1 = fmaf(w1, a1.y, d1); d1 = fmaf(w2, a1.z, d1); d1 = fmaf(w3, a1.w, d1);
                d2 = fmaf(w0, a2.x, d2); d2 = fmaf(w1, a2.y, d2); d2 = fmaf(w2, a2.z, d2); d2 = fmaf(w3, a2.w, d2);
                d3 = fmaf(w0, a3.x, d3); d3 = fmaf(w1, a3.y, d3); d3 = fmaf(w2, a3.z, d3); d3 = fmaf(w3, a3.w, d3);
            }
            float e0 = fmaf(-2.f, d0, sqs[jj+0]);
            float e1 = fmaf(-2.f, d1, sqs[jj+1]);
            float e2 = fmaf(-2.f, d2, sqs[jj+2]);
            float e3 = fmaf(-2.f, d3, sqs[jj+3]);
            int j0 = jt + jj;
            if (j0+0 != i) upd6(e0, j0+0, bd, bi);
            if (j0+1 != i) upd6(e1, j0+1, bd, bi);
            if (j0+2 != i) upd6(e2, j0+2, bd, bi);
            if (j0+3 != i) upd6(e3, j0+3, bd, bi);
        }
        for (; jj < tile; jj++){
            float d0 = 0.f;
#pragma unroll
            for (int q = 0; q < Q; q++){
                float4 a0 = xs[jj*Q+q];
                d0 = fmaf(xi[4*q+0], a0.x, d0); d0 = fmaf(xi[4*q+1], a0.y, d0);
                d0 = fmaf(xi[4*q+2], a0.z, d0); d0 = fmaf(xi[4*q+3], a0.w, d0);
            }
            float e0 = fmaf(-2.f, d0, sqs[jj]);
            int j0 = jt + jj;
            if (j0 != i) upd6(e0, j0, bd, bi);
        }
    }
    if (i < n){
#pragma unroll
        for (int k = 0; k < KNN; k++) outidx[i*KNN+k] = bi[k];
    }
}

// ---------------- dynamic edge conv: y[i] = relu(max_j ( relu([xi, xj-xi]@W1+b1) @ W2 + b2 )) ----------------
template<int F>
__global__ void edgeconv_kernel(const float* __restrict__ X, const int* __restrict__ idx,
                                const float* __restrict__ W1, const float* __restrict__ b1,
                                const float* __restrict__ W2, const float* __restrict__ b2,
                                int n, float* __restrict__ Y, float* __restrict__ sqout){
    __shared__ float sW1[2*F*32];
    __shared__ float sb1[32];
    __shared__ float sW2[32*32];
    __shared__ float sb2[32];
    for (int t = threadIdx.x; t < 2*F*32; t += blockDim.x) sW1[t] = W1[t];
    for (int t = threadIdx.x; t < 32*32;  t += blockDim.x) sW2[t] = W2[t];
    if (threadIdx.x < 32){ sb1[threadIdx.x] = b1[threadIdx.x]; sb2[threadIdx.x] = b2[threadIdx.x]; }
    __syncthreads();
    int i = blockIdx.x*blockDim.x + threadIdx.x;
    if (i >= n) return;

    // base = b1 + xi @ W1[0:F]   (shared across all 6 neighbors)
    float base[32];
#pragma unroll
    for (int c = 0; c < 32; c++) base[c] = sb1[c];
    for (int d = 0; d < F; d++){
        float v = X[i*F+d];
#pragma unroll
        for (int c = 0; c < 32; c++) base[c] = fmaf(v, sW1[d*32+c], base[c]);
    }
    float acc[32];
#pragma unroll
    for (int c = 0; c < 32; c++) acc[c] = -INFINITY;

    for (int kk = 0; kk < KNN; kk++){
        int j = idx[i*KNN+kk];
        float h[32];
#pragma unroll
        for (int c = 0; c < 32; c++) h[c] = base[c];
        for (int d = 0; d < F; d++){
            float v = X[j*F+d] - X[i*F+d];
#pragma unroll
            for (int c = 0; c < 32; c++) h[c] = fmaf(v, sW1[(F+d)*32+c], h[c]);
        }
#pragma unroll
        for (int c = 0; c < 32; c++) h[c] = fmaxf(h[c], 0.f);
#pragma unroll
        for (int c = 0; c < 32; c++){
            float o = sb2[c];
#pragma unroll
            for (int k = 0; k < 32; k++) o = fmaf(h[k], sW2[k*32+c], o);
            acc[c] = fmaxf(acc[c], o);
        }
    }
    float sqv = 0.f;
#pragma unroll
    for (int c = 0; c < 32; c++){
        float r = fmaxf(acc[c], 0.f);
        Y[i*32+c] = r;
        sqv = fmaf(r, r, sqv);
    }
    if (sqout) sqout[i] = sqv;
}

// ---------------- cat0 = [x1 | y1]; agg2 init = cat0 (self loop) ----------------
__global__ void cat0_kernel(int n){
    int t = blockIdx.x*blockDim.x + threadIdx.x;
    if (t >= n*48) return;
    int i = t / 48, d = t % 48;
    float v = (d < 16) ? g_x1[i*16+d] : g_y1[i*32 + (d-16)];
    g_cat0[t] = v;
    g_agg2[t] = v;
}

__global__ void scatter2_kernel(const int* __restrict__ src, const int* __restrict__ dst, int E){
    int t = blockIdx.x*blockDim.x + threadIdx.x;
    int e = t / 12;
    if (e >= E) return;
    int q = t % 12;
    int s = src[e], d = dst[e];
    float4 v = reinterpret_cast<const float4*>(g_cat0)[s*12 + q];
    float* a = &g_agg2[d*48 + q*4];
    atomicAdd(a+0, v.x); atomicAdd(a+1, v.y); atomicAdd(a+2, v.z); atomicAdd(a+3, v.w);
}

// ---------------- MLP layer 1: h1 = relu([x3 | y2] @ l1W + l1b) ----------------
__global__ void mlp1_kernel(const float* __restrict__ W, const float* __restrict__ b, int n){
    __shared__ float sW[96*96];
    __shared__ float sb[96];
    for (int t = threadIdx.x; t < 96*96; t += blockDim.x) sW[t] = W[t];
    for (int t = threadIdx.x; t < 96;    t += blockDim.x) sb[t] = b[t];
    __syncthreads();
    int i = blockIdx.x*blockDim.x + threadIdx.x;
    if (i >= n) return;
    float acc[96];
#pragma unroll
    for (int c = 0; c < 96; c++) acc[c] = sb[c];
    for (int d = 0; d < 64; d++){
        float v = g_x3[i*64+d];
#pragma unroll
        for (int c = 0; c < 96; c++) acc[c] = fmaf(v, sW[d*96+c], acc[c]);
    }
    for (int d = 0; d < 32; d++){
        float v = g_y2[i*32+d];
#pragma unroll
        for (int c = 0; c < 96; c++) acc[c] = fmaf(v, sW[(64+d)*96+c], acc[c]);
    }
#pragma unroll
    for (int c = 0; c < 96; c++) g_h1[i*96+c] = fmaxf(acc[c], 0.f);
}

// ---------------- MLP layers 2..out: 96->32->8->1, sigmoid ----------------
__global__ void mlp2_kernel(const float* __restrict__ W2, const float* __restrict__ b2,
                            const float* __restrict__ W3, const float* __restrict__ b3,
                            const float* __restrict__ Wo, const float* __restrict__ bo,
                            int n, float* __restrict__ out){
    __shared__ float sW2[96*32]; __shared__ float sb2v[32];
    __shared__ float sW3[32*8];  __shared__ float sb3v[8];
    __shared__ float sWo[8];     __shared__ float sbo;
    for (int t = threadIdx.x; t < 96*32; t += blockDim.x) sW2[t] = W2[t];
    for (int t = threadIdx.x; t < 32*8;  t += blockDim.x) sW3[t] = W3[t];
    if (threadIdx.x < 32) sb2v[threadIdx.x] = b2[threadIdx.x];
    if (threadIdx.x < 8){ sb3v[threadIdx.x] = b3[threadIdx.x]; sWo[threadIdx.x] = Wo[threadIdx.x]; }
    if (threadIdx.x == 0) sbo = bo[0];
    __syncthreads();
    int i = blockIdx.x*blockDim.x + threadIdx.x;
    if (i >= n) return;
    float h[32];
#pragma unroll
    for (int c = 0; c < 32; c++) h[c] = sb2v[c];
    for (int d = 0; d < 96; d++){
        float v = g_h1[i*96+d];
#pragma unroll
        for (int c = 0; c < 32; c++) h[c] = fmaf(v, sW2[d*32+c], h[c]);
    }
#pragma unroll
    for (int c = 0; c < 32; c++) h[c] = fmaxf(h[c], 0.f);
    float g[8];
#pragma unroll
    for (int c = 0; c < 8; c++){
        float o = sb3v[c];
#pragma unroll
        for (int k = 0; k < 32; k++) o = fmaf(h[k], sW3[k*8+c], o);
        g[c] = fmaxf(o, 0.f);
    }
    float z = sbo;
#pragma unroll
    for (int c = 0; c < 8; c++) z = fmaf(g[c], sWo[c], z);
    out[i] = 1.0f / (1.0f + expf(-z));
}

// ---------------- launch ----------------
extern "C" void kernel_launch(void* const* d_in, const int* in_sizes, int n_in,
                              void* d_out, int out_size){
    const float* x   = (const float*)d_in[0];
    const int*   ei  = (const int*)  d_in[1];
    int n = in_sizes[0] / 16;
    int E = in_sizes[1] / 2;
    const int* src = ei;
    const int* dst = ei + E;

    const float* cW1 = (const float*)d_in[2];
    const float* cb1 = (const float*)d_in[5];
    const float* cW3 = (const float*)d_in[6];
    const float* cb3 = (const float*)d_in[9];
    const float* e1W1=(const float*)d_in[10]; const float* e1b1=(const float*)d_in[11];
    const float* e1W2=(const float*)d_in[12]; const float* e1b2=(const float*)d_in[13];
    const float* e2W1=(const float*)d_in[14]; const float* e2b1=(const float*)d_in[15];
    const float* e2W2=(const float*)d_in[16]; const float* e2b2=(const float*)d_in[17];
    const float* l1W =(const float*)d_in[18]; const float* l1b =(const float*)d_in[19];
    const float* l2W =(const float*)d_in[20]; const float* l2b =(const float*)d_in[21];
    const float* l3W =(const float*)d_in[22]; const float* l3b =(const float*)d_in[23];
    const float* oW  =(const float*)d_in[24]; const float* ob  =(const float*)d_in[25];
    float* out = (float*)d_out;

    void *p_agg1, *p_x1, *p_sq1, *p_idx1, *p_y1, *p_sq2, *p_agg2, *p_idx2, *p_x3, *p_y2;
    cudaGetSymbolAddress(&p_agg1, g_agg1);
    cudaGetSymbolAddress(&p_x1,   g_x1);
    cudaGetSymbolAddress(&p_sq1,  g_sq1);
    cudaGetSymbolAddress(&p_idx1, g_idx1);
    cudaGetSymbolAddress(&p_y1,   g_y1);
    cudaGetSymbolAddress(&p_sq2,  g_sq2);
    cudaGetSymbolAddress(&p_agg2, g_agg2);
    cudaGetSymbolAddress(&p_idx2, g_idx2);
    cudaGetSymbolAddress(&p_x3,   g_x3);
    cudaGetSymbolAddress(&p_y2,   g_y2);

    int nb = (n + 127) / 128;

    // FeaSt 1 (heads=1 => attention == 1 => segment-mean then GEMM)
    init1_kernel<<<(n*16 + 255)/256, 256>>>(x, n);
    scatter1_kernel<<<(E*4 + 255)/256, 256>>>(src, dst, x, E);
    feast_kernel<16,16,true><<<nb,128>>>((const float*)p_agg1, cW1, cb1, n,
                                         (float*)p_x1, (float*)p_sq1);
    // kNN on x1 (dim 16) + edge conv 1
    knn_kernel<16><<<nb,128>>>((const float*)p_x1, (const float*)p_sq1, n, (int*)p_idx1);
    edgeconv_kernel<16><<<nb,128>>>((const float*)p_x1, (const int*)p_idx1,
                                    e1W1, e1b1, e1W2, e1b2, n,
                                    (float*)p_y1, (float*)p_sq2);
    // FeaSt 2 on cat0 = [x1|y1]
    cat0_kernel<<<(n*48 + 255)/256, 256>>>(n);
    scatter2_kernel<<<(E*12 + 255)/256, 256>>>(src, dst, E);
    feast_kernel<48,64,false><<<nb,128>>>((const float*)p_agg2, cW3, cb3, n,
                                          (float*)p_x3, nullptr);
    // kNN on y1 (dim 32) + edge conv 2
    knn_kernel<32><<<nb,128>>>((const float*)p_y1, (const float*)p_sq2, n, (int*)p_idx2);
    edgeconv_kernel<32><<<nb,128>>>((const float*)p_y1, (const int*)p_idx2,
                                    e2W1, e2b1, e2W2, e2b2, n,
                                    (float*)p_y2, nullptr);
    // Final MLP
    mlp1_kernel<<<nb,128>>>(l1W, l1b, n);
    mlp2_kernel<<<nb,128>>>(l2W, l2b, l3W, l3b, oW, ob, n, out);
}

// round 2
// speedup vs baseline: 2.0783x; 2.0783x over previous
#include <cuda_runtime.h>
#include <math.h>

#define NMAX 20000
#define KNN 6
#define NPART 16

// ---------------- scratch (device globals; no allocation allowed) ----------------
__device__ __align__(16) float g_cnt [NMAX];
__device__ __align__(16) float g_agg1[NMAX*16];
__device__ __align__(16) float g_x1  [NMAX*16];
__device__ __align__(16) float g_sq1 [NMAX];
__device__ __align__(16) int   g_idx1[NMAX*KNN];
__device__ __align__(16) float g_y1  [NMAX*32];
__device__ __align__(16) float g_sq2 [NMAX];
__device__ __align__(16) float g_cat0[NMAX*48];
__device__ __align__(16) float g_agg2[NMAX*48];
__device__ __align__(16) int   g_idx2[NMAX*KNN];
__device__ __align__(16) float g_x3  [NMAX*64];
__device__ __align__(16) float g_y2  [NMAX*32];
__device__ __align__(16) float g_h1  [NMAX*96];
__device__ __align__(16) float g_cd  [NMAX*NPART*KNN];
__device__ __align__(16) int   g_ci  [NMAX*NPART*KNN];

// ---------------- init: agg1 = x (self loop), cnt = 1 ----------------
__global__ void init1_kernel(const float* __restrict__ x, int n){
    int t = blockIdx.x*blockDim.x + threadIdx.x;
    if (t < n*16) g_agg1[t] = x[t];
    if (t < n)    g_cnt[t]  = 1.0f;
}

// ---------------- scatter-add of x[src] into agg1[dst], count edges ----------------
__global__ void scatter1_kernel(const int* __restrict__ src, const int* __restrict__ dst,
                                const float* __restrict__ x, int E){
    int t = blockIdx.x*blockDim.x + threadIdx.x;
    int e = t >> 2;
    if (e >= E) return;
    int q = t & 3;
    int s = src[e], d = dst[e];
    if (q == 0) atomicAdd(&g_cnt[d], 1.0f);
    float4 v = reinterpret_cast<const float4*>(x)[s*4 + q];
    float* a = &g_agg1[d*16 + q*4];
    atomicAdd(a+0, v.x); atomicAdd(a+1, v.y); atomicAdd(a+2, v.z); atomicAdd(a+3, v.w);
}

// ---------------- feast output: out = relu((agg/cnt) @ W + b), optional ||row||^2 ----------------
template<int IN, int OUT, bool WSQ>
__global__ void feast_kernel(const float* __restrict__ agg, const float* __restrict__ W,
                             const float* __restrict__ b, int n,
                             float* __restrict__ out, float* __restrict__ sqout){
    __shared__ float sW[IN*OUT];
    __shared__ float sb[OUT];
    for (int t = threadIdx.x; t < IN*OUT; t += blockDim.x) sW[t] = W[t];
    for (int t = threadIdx.x; t < OUT;    t += blockDim.x) sb[t] = b[t];
    __syncthreads();
    int i = blockIdx.x*blockDim.x + threadIdx.x;
    if (i >= n) return;
    float inv = 1.0f / g_cnt[i];
    float acc[OUT];
#pragma unroll
    for (int c = 0; c < OUT; c++) acc[c] = sb[c];
    for (int d = 0; d < IN; d++){
        float v = agg[i*IN+d] * inv;
#pragma unroll
        for (int c = 0; c < OUT; c++) acc[c] = fmaf(v, sW[d*OUT+c], acc[c]);
    }
    float sq = 0.f;
#pragma unroll
    for (int c = 0; c < OUT; c++){
        float r = fmaxf(acc[c], 0.f);
        out[i*OUT+c] = r;
        sq = fmaf(r, r, sq);
    }
    if (WSQ) sqout[i] = sq;
}

// ---------------- streaming top-6 insertion (ascending-j scan => lower index wins ties) ----------------
__device__ __forceinline__ void upd6(float d, int j, float bd[KNN], int bi[KNN]){
    if (d < bd[KNN-1]){
        bd[KNN-1] = d; bi[KNN-1] = j;
#pragma unroll
        for (int k = KNN-1; k > 0; k--){
            if (bd[k] < bd[k-1]){
                float td = bd[k]; bd[k] = bd[k-1]; bd[k-1] = td;
                int   ti = bi[k]; bi[k] = bi[k-1]; bi[k-1] = ti;
            }
        }
    }
}

// ---------------- partitioned pairwise-distance + local top-6 ----------------
// grid: (ceil(n/128), NPART). Each CTA scans its j-slice and emits local top-6
// candidates per query node. Distances are computed with the identical FMA
// sequence as a full scan, so candidate keys are bit-exact.
template<int DIM>
__global__ void knn_part_kernel(const float* __restrict__ X, const float* __restrict__ sq,
                                int n, int chunk){
    const int TS = 128;
    const int Q  = DIM/4;
    __shared__ float4 xs[TS*Q];
    __shared__ float  sqs[TS];
    int i = blockIdx.x*blockDim.x + threadIdx.x;
    int p = blockIdx.y;
    int jbeg = p * chunk;
    int jend = min(n, jbeg + chunk);

    float xi[DIM];
    if (i < n){
#pragma unroll
        for (int d = 0; d < DIM; d++) xi[d] = X[i*DIM+d];
    }
    float bd[KNN]; int bi[KNN];
#pragma unroll
    for (int k = 0; k < KNN; k++){ bd[k] = INFINITY; bi[k] = -1; }

    for (int jt = jbeg; jt < jend; jt += TS){
        int tile = min(TS, jend - jt);
        __syncthreads();
        for (int t = threadIdx.x; t < tile*Q; t += blockDim.x)
            xs[t] = reinterpret_cast<const float4*>(X)[jt*Q + t];
        for (int t = threadIdx.x; t < tile; t += blockDim.x)
            sqs[t] = sq[jt + t];
        __syncthreads();
        if (i >= n) continue;

        int jj = 0;
        for (; jj + 4 <= tile; jj += 4){
            float d0=0.f, d1=0.f, d2=0.f, d3=0.f;
#pragma unroll
            for (int q = 0; q < Q; q++){
                float4 a0 = xs[(jj+0)*Q+q];
                float4 a1 = xs[(jj+1)*Q+q];
                float4 a2 = xs[(jj+2)*Q+q];
                float4 a3 = xs[(jj+3)*Q+q];
                float w0 = xi[4*q+0], w1 = xi[4*q+1], w2 = xi[4*q+2], w3 = xi[4*q+3];
                d0 = fmaf(w0, a0.x, d0); d0 = fmaf(w1, a0.y, d0); d0 = fmaf(w2, a0.z, d0); d0 = fmaf(w3, a0.w, d0);
                d1 = fmaf(w0, a1.x, d1); d1 = fmaf(w1, a1.y, d1); d1 = fmaf(w2, a1.z, d1); d1 = fmaf(w3, a1.w, d1);
                d2 = fmaf(w0, a2.x, d2); d2 = fmaf(w1, a2.y, d2); d2 = fmaf(w2, a2.z, d2); d2 = fmaf(w3, a2.w, d2);
                d3 = fmaf(w0, a3.x, d3); d3 = fmaf(w1, a3.y, d3); d3 = fmaf(w2, a3.z, d3); d3 = fmaf(w3, a3.w, d3);
            }
            float e0 = fmaf(-2.f, d0, sqs[jj-jbeg+jt+0 - jt]);
            // (kept simple below — recompute shared index directly)
            e0 = fmaf(-2.f, d0, sqs[jj+0]);
            float e1 = fmaf(-2.f, d1, sqs[jj+1]);
            float e2 = fmaf(-2.f, d2, sqs[jj+2]);
            float e3 = fmaf(-2.f, d3, sqs[jj+3]);
            int j0 = jt + jj;
            if (j0+0 != i) upd6(e0, j0+0, bd, bi);
            if (j0+1 != i) upd6(e1, j0+1, bd, bi);
            if (j0+2 != i) upd6(e2, j0+2, bd, bi);
            if (j0+3 != i) upd6(e3, j0+3, bd, bi);
        }
        for (; jj < tile; jj++){
            float d0 = 0.f;
#pragma unroll
            for (int q = 0; q < Q; q++){
                float4 a0 = xs[jj*Q+q];
                d0 = fmaf(xi[4*q+0], a0.x, d0); d0 = fmaf(xi[4*q+1], a0.y, d0);
                d0 = fmaf(xi[4*q+2], a0.z, d0); d0 = fmaf(xi[4*q+3], a0.w, d0);
            }
            float e0 = fmaf(-2.f, d0, sqs[jj]);
            int j0 = jt + jj;
            if (j0 != i) upd6(e0, j0, bd, bi);
        }
    }
    if (i < n){
        int base = (i*NPART + p)*KNN;
#pragma unroll
        for (int k = 0; k < KNN; k++){ g_cd[base+k] = bd[k]; g_ci[base+k] = bi[k]; }
    }
}

// ---------------- merge NPART*6 candidates -> global top-6 per node ----------------
// Key = (distance, index) lexicographic: reproduces ascending-scan tie semantics.
__global__ void knn_merge_kernel(int n, int* __restrict__ outidx){
    int i = blockIdx.x*blockDim.x + threadIdx.x;
    if (i >= n) return;
    float bd[KNN]; unsigned bi[KNN];
#pragma unroll
    for (int k = 0; k < KNN; k++){ bd[k] = INFINITY; bi[k] = 0xFFFFFFFFu; }
    int base = i*NPART*KNN;
    for (int c = 0; c < NPART*KNN; c++){
        float d = g_cd[base+c];
        int   jraw = g_ci[base+c];
        if (jraw < 0) continue;
        unsigned j = (unsigned)jraw;
        if (d < bd[KNN-1] || (d == bd[KNN-1] && j < bi[KNN-1])){
            bd[KNN-1] = d; bi[KNN-1] = j;
#pragma unroll
            for (int k = KNN-1; k > 0; k--){
                bool sw = (bd[k] < bd[k-1]) || (bd[k] == bd[k-1] && bi[k] < bi[k-1]);
                if (sw){
                    float td = bd[k]; bd[k] = bd[k-1]; bd[k-1] = td;
                    unsigned ti = bi[k]; bi[k] = bi[k-1]; bi[k-1] = ti;
                }
            }
        }
    }
#pragma unroll
    for (int k = 0; k < KNN; k++) outidx[i*KNN+k] = (int)bi[k];
}

// ---------------- dynamic edge conv: y[i] = relu(max_j ( relu([xi, xj-xi]@W1+b1) @ W2 + b2 )) ----------------
template<int F>
__global__ void edgeconv_kernel(const float* __restrict__ X, const int* __restrict__ idx,
                                const float* __restrict__ W1, const float* __restrict__ b1,
                                const float* __restrict__ W2, const float* __restrict__ b2,
                                int n, float* __restrict__ Y, float* __restrict__ sqout){
    __shared__ float sW1[2*F*32];
    __shared__ float sb1[32];
    __shared__ float sW2[32*32];
    __shared__ float sb2[32];
    for (int t = threadIdx.x; t < 2*F*32; t += blockDim.x) sW1[t] = W1[t];
    for (int t = threadIdx.x; t < 32*32;  t += blockDim.x) sW2[t] = W2[t];
    if (threadIdx.x < 32){ sb1[threadIdx.x] = b1[threadIdx.x]; sb2[threadIdx.x] = b2[threadIdx.x]; }
    __syncthreads();
    int i = blockIdx.x*blockDim.x + threadIdx.x;
    if (i >= n) return;

    float base[32];
#pragma unroll
    for (int c = 0; c < 32; c++) base[c] = sb1[c];
    for (int d = 0; d < F; d++){
        float v = X[i*F+d];
#pragma unroll
        for (int c = 0; c < 32; c++) base[c] = fmaf(v, sW1[d*32+c], base[c]);
    }
    float acc[32];
#pragma unroll
    for (int c = 0; c < 32; c++) acc[c] = -INFINITY;

    for (int kk = 0; kk < KNN; kk++){
        int j = idx[i*KNN+kk];
        float h[32];
#pragma unroll
        for (int c = 0; c < 32; c++) h[c] = base[c];
        for (int d = 0; d < F; d++){
            float v = X[j*F+d] - X[i*F+d];
#pragma unroll
            for (int c = 0; c < 32; c++) h[c] = fmaf(v, sW1[(F+d)*32+c], h[c]);
        }
#pragma unroll
        for (int c = 0; c < 32; c++) h[c] = fmaxf(h[c], 0.f);
#pragma unroll
        for (int c = 0; c < 32; c++){
            float o = sb2[c];
#pragma unroll
            for (int k = 0; k < 32; k++) o = fmaf(h[k], sW2[k*32+c], o);
            acc[c] = fmaxf(acc[c], o);
        }
    }
    float sqv = 0.f;
#pragma unroll
    for (int c = 0; c < 32; c++){
        float r = fmaxf(acc[c], 0.f);
        Y[i*32+c] = r;
        sqv = fmaf(r, r, sqv);
    }
    if (sqout) sqout[i] = sqv;
}

// ---------------- cat0 = [x1 | y1]; agg2 init = cat0 (self loop) ----------------
__global__ void cat0_kernel(int n){
    int t = blockIdx.x*blockDim.x + threadIdx.x;
    if (t >= n*48) return;
    int i = t / 48, d = t % 48;
    float v = (d < 16) ? g_x1[i*16+d] : g_y1[i*32 + (d-16)];
    g_cat0[t] = v;
    g_agg2[t] = v;
}

__global__ void scatter2_kernel(const int* __restrict__ src, const int* __restrict__ dst, int E){
    int t = blockIdx.x*blockDim.x + threadIdx.x;
    int e = t / 12;
    if (e >= E) return;
    int q = t % 12;
    int s = src[e], d = dst[e];
    float4 v = reinterpret_cast<const float4*>(g_cat0)[s*12 + q];
    float* a = &g_agg2[d*48 + q*4];
    atomicAdd(a+0, v.x); atomicAdd(a+1, v.y); atomicAdd(a+2, v.z); atomicAdd(a+3, v.w);
}

// ---------------- MLP layer 1: h1 = relu([x3 | y2] @ l1W + l1b) ----------------
__global__ void mlp1_kernel(const float* __restrict__ W, const float* __restrict__ b, int n){
    __shared__ float sW[96*96];
    __shared__ float sb[96];
    for (int t = threadIdx.x; t < 96*96; t += blockDim.x) sW[t] = W[t];
    for (int t = threadIdx.x; t < 96;    t += blockDim.x) sb[t] = b[t];
    __syncthreads();
    int i = blockIdx.x*blockDim.x + threadIdx.x;
    if (i >= n) return;
    float acc[96];
#pragma unroll
    for (int c = 0; c < 96; c++) acc[c] = sb[c];
    for (int d = 0; d < 64; d++){
        float v = g_x3[i*64+d];
#pragma unroll
        for (int c = 0; c < 96; c++) acc[c] = fmaf(v, sW[d*96+c], acc[c]);
    }
    for (int d = 0; d < 32; d++){
        float v = g_y2[i*32+d];
#pragma unroll
        for (int c = 0; c < 96; c++) acc[c] = fmaf(v, sW[(64+d)*96+c], acc[c]);
    }
#pragma unroll
    for (int c = 0; c < 96; c++) g_h1[i*96+c] = fmaxf(acc[c], 0.f);
}

// ---------------- MLP layers 2..out: 96->32->8->1, sigmoid ----------------
__global__ void mlp2_kernel(const float* __restrict__ W2, const float* __restrict__ b2,
                            const float* __restrict__ W3, const float* __restrict__ b3,
                            const float* __restrict__ Wo, const float* __restrict__ bo,
                            int n, float* __restrict__ out){
    __shared__ float sW2[96*32]; __shared__ float sb2v[32];
    __shared__ float sW3[32*8];  __shared__ float sb3v[8];
    __shared__ float sWo[8];     __shared__ float sbo;
    for (int t = threadIdx.x; t < 96*32; t += blockDim.x) sW2[t] = W2[t];
    for (int t = threadIdx.x; t < 32*8;  t += blockDim.x) sW3[t] = W3[t];
    if (threadIdx.x < 32) sb2v[threadIdx.x] = b2[threadIdx.x];
    if (threadIdx.x < 8){ sb3v[threadIdx.x] = b3[threadIdx.x]; sWo[threadIdx.x] = Wo[threadIdx.x]; }
    if (threadIdx.x == 0) sbo = bo[0];
    __syncthreads();
    int i = blockIdx.x*blockDim.x + threadIdx.x;
    if (i >= n) return;
    float h[32];
#pragma unroll
    for (int c = 0; c < 32; c++) h[c] = sb2v[c];
    for (int d = 0; d < 96; d++){
        float v = g_h1[i*96+d];
#pragma unroll
        for (int c = 0; c < 32; c++) h[c] = fmaf(v, sW2[d*32+c], h[c]);
    }
#pragma unroll
    for (int c = 0; c < 32; c++) h[c] = fmaxf(h[c], 0.f);
    float g[8];
#pragma unroll
    for (int c = 0; c < 8; c++){
        float o = sb3v[c];
#pragma unroll
        for (int k = 0; k < 32; k++) o = fmaf(h[k], sW3[k*8+c], o);
        g[c] = fmaxf(o, 0.f);
    }
    float z = sbo;
#pragma unroll
    for (int c = 0; c < 8; c++) z = fmaf(g[c], sWo[c], z);
    out[i] = 1.0f / (1.0f + expf(-z));
}

// ---------------- launch ----------------
extern "C" void kernel_launch(void* const* d_in, const int* in_sizes, int n_in,
                              void* d_out, int out_size){
    const float* x   = (const float*)d_in[0];
    const int*   ei  = (const int*)  d_in[1];
    int n = in_sizes[0] / 16;
    int E = in_sizes[1] / 2;
    const int* src = ei;
    const int* dst = ei + E;

    const float* cW1 = (const float*)d_in[2];
    const float* cb1 = (const float*)d_in[5];
    const float* cW3 = (const float*)d_in[6];
    const float* cb3 = (const float*)d_in[9];
    const float* e1W1=(const float*)d_in[10]; const float* e1b1=(const float*)d_in[11];
    const float* e1W2=(const float*)d_in[12]; const float* e1b2=(const float*)d_in[13];
    const float* e2W1=(const float*)d_in[14]; const float* e2b1=(const float*)d_in[15];
    const float* e2W2=(const float*)d_in[16]; const float* e2b2=(const float*)d_in[17];
    const float* l1W =(const float*)d_in[18]; const float* l1b =(const float*)d_in[19];
    const float* l2W =(const float*)d_in[20]; const float* l2b =(const float*)d_in[21];
    const float* l3W =(const float*)d_in[22]; const float* l3b =(const float*)d_in[23];
    const float* oW  =(const float*)d_in[24]; const float* ob  =(const float*)d_in[25];
    float* out = (float*)d_out;

    void *p_agg1, *p_x1, *p_sq1, *p_idx1, *p_y1, *p_sq2, *p_agg2, *p_idx2, *p_x3, *p_y2;
    cudaGetSymbolAddress(&p_agg1, g_agg1);
    cudaGetSymbolAddress(&p_x1,   g_x1);
    cudaGetSymbolAddress(&p_sq1,  g_sq1);
    cudaGetSymbolAddress(&p_idx1, g_idx1);
    cudaGetSymbolAddress(&p_y1,   g_y1);
    cudaGetSymbolAddress(&p_sq2,  g_sq2);
    cudaGetSymbolAddress(&p_agg2, g_agg2);
    cudaGetSymbolAddress(&p_idx2, g_idx2);
    cudaGetSymbolAddress(&p_x3,   g_x3);
    cudaGetSymbolAddress(&p_y2,   g_y2);

    int nb = (n + 127) / 128;
    int chunk = (n + NPART - 1) / NPART;
    dim3 knngrid(nb, NPART);

    // FeaSt 1 (heads=1 => attention == 1 => segment-mean then GEMM)
    init1_kernel<<<(n*16 + 255)/256, 256>>>(x, n);
    scatter1_kernel<<<(E*4 + 255)/256, 256>>>(src, dst, x, E);
    feast_kernel<16,16,true><<<nb,128>>>((const float*)p_agg1, cW1, cb1, n,
                                         (float*)p_x1, (float*)p_sq1);
    // kNN on x1 (dim 16): partitioned + merge
    knn_part_kernel<16><<<knngrid,128>>>((const float*)p_x1, (const float*)p_sq1, n, chunk);
    knn_merge_kernel<<<(n+255)/256,256>>>(n, (int*)p_idx1);
    edgeconv_kernel<16><<<nb,128>>>((const float*)p_x1, (const int*)p_idx1,
                                    e1W1, e1b1, e1W2, e1b2, n,
                                    (float*)p_y1, (float*)p_sq2);
    // FeaSt 2 on cat0 = [x1|y1]
    cat0_kernel<<<(n*48 + 255)/256, 256>>>(n);
    scatter2_kernel<<<(E*12 + 255)/256, 256>>>(src, dst, E);
    feast_kernel<48,64,false><<<nb,128>>>((const float*)p_agg2, cW3, cb3, n,
                                          (float*)p_x3, nullptr);
    // kNN on y1 (dim 32): partitioned + merge
    knn_part_kernel<32><<<knngrid,128>>>((const float*)p_y1, (const float*)p_sq2, n, chunk);
    knn_merge_kernel<<<(n+255)/256,256>>>(n, (int*)p_idx2);
    edgeconv_kernel<32><<<nb,128>>>((const float*)p_y1, (const int*)p_idx2,
                                    e2W1, e2b1, e2W2, e2b2, n,
                                    (float*)p_y2, nullptr);
    // Final MLP
    mlp1_kernel<<<nb,128>>>(l1W, l1b, n);
    mlp2_kernel<<<nb,128>>>(l2W, l2b, l3W, l3b, oW, ob, n, out);
}

// round 3
// speedup vs baseline: 2.1894x; 1.0535x over previous
#include <cuda_runtime.h>
#include <math.h>

#define NMAX 20000
#define KNN 6
#define NPART 16

typedef unsigned long long u64;

// ---------------- scratch (device globals; no allocation allowed) ----------------
__device__ __align__(16) float g_cnt [NMAX];
__device__ __align__(16) float g_agg1[NMAX*16];
__device__ __align__(16) float g_x1  [NMAX*16];
__device__ __align__(16) float g_sq1 [NMAX];
__device__ __align__(16) int   g_idx1[NMAX*KNN];
__device__ __align__(16) float g_y1  [NMAX*32];
__device__ __align__(16) float g_sq2 [NMAX];
__device__ __align__(16) float g_cat0[NMAX*48];
__device__ __align__(16) float g_agg2[NMAX*48];
__device__ __align__(16) int   g_idx2[NMAX*KNN];
__device__ __align__(16) float g_x3  [NMAX*64];
__device__ __align__(16) float g_y2  [NMAX*32];
__device__ __align__(16) float g_h1  [NMAX*96];
__device__ __align__(16) float g_cd  [NMAX*NPART*KNN];
__device__ __align__(16) int   g_ci  [NMAX*NPART*KNN];

// ---------------- packed f32x2 helpers ----------------
__device__ __forceinline__ u64 f2fma(u64 a, u64 b, u64 c){
    u64 d;
    asm("fma.rn.f32x2 %0, %1, %2, %3;" : "=l"(d) : "l"(a), "l"(b), "l"(c));
    return d;
}
__device__ __forceinline__ float f2hadd(u64 a){
    float lo, hi;
    asm("mov.b64 {%0, %1}, %2;" : "=f"(lo), "=f"(hi) : "l"(a));
    return lo + hi;
}

// ---------------- init: agg1 = x (self loop), cnt = 1 ----------------
__global__ void init1_kernel(const float* __restrict__ x, int n){
    int t = blockIdx.x*blockDim.x + threadIdx.x;
    if (t < n*16) g_agg1[t] = x[t];
    if (t < n)    g_cnt[t]  = 1.0f;
}

// ---------------- scatter-add of x[src] into agg1[dst], count edges ----------------
__global__ void scatter1_kernel(const int* __restrict__ src, const int* __restrict__ dst,
                                const float* __restrict__ x, int E){
    int t = blockIdx.x*blockDim.x + threadIdx.x;
    int e = t >> 2;
    if (e >= E) return;
    int q = t & 3;
    int s = src[e], d = dst[e];
    if (q == 0) atomicAdd(&g_cnt[d], 1.0f);
    float4 v = reinterpret_cast<const float4*>(x)[s*4 + q];
    float* a = &g_agg1[d*16 + q*4];
    atomicAdd(a+0, v.x); atomicAdd(a+1, v.y); atomicAdd(a+2, v.z); atomicAdd(a+3, v.w);
}

// ---------------- feast: out = relu((agg/cnt) @ W + b), optional ||row||^2 ----------------
template<int IN, int OUT, bool WSQ>
__global__ void feast_kernel(const float* __restrict__ agg, const float* __restrict__ W,
                             const float* __restrict__ b, int n,
                             float* __restrict__ out, float* __restrict__ sqout){
    __shared__ float sW[IN*OUT];
    __shared__ float sb[OUT];
    for (int t = threadIdx.x; t < IN*OUT; t += blockDim.x) sW[t] = W[t];
    for (int t = threadIdx.x; t < OUT;    t += blockDim.x) sb[t] = b[t];
    __syncthreads();
    int i = blockIdx.x*blockDim.x + threadIdx.x;
    if (i >= n) return;
    float inv = 1.0f / g_cnt[i];
    float acc[OUT];
#pragma unroll
    for (int c = 0; c < OUT; c++) acc[c] = sb[c];
    for (int d = 0; d < IN; d++){
        float v = agg[i*IN+d] * inv;
#pragma unroll
        for (int c = 0; c < OUT; c++) acc[c] = fmaf(v, sW[d*OUT+c], acc[c]);
    }
    float sq = 0.f;
#pragma unroll
    for (int c = 0; c < OUT; c++){
        float r = fmaxf(acc[c], 0.f);
        out[i*OUT+c] = r;
        sq = fmaf(r, r, sq);
    }
    if (WSQ) sqout[i] = sq;
}

// ---------------- streaming top-6 insertion ----------------
__device__ __forceinline__ void upd6(float d, int j, float bd[KNN], int bi[KNN]){
    if (d < bd[KNN-1]){
        bd[KNN-1] = d; bi[KNN-1] = j;
#pragma unroll
        for (int k = KNN-1; k > 0; k--){
            if (bd[k] < bd[k-1]){
                float td = bd[k]; bd[k] = bd[k-1]; bd[k-1] = td;
                int   ti = bi[k]; bi[k] = bi[k-1]; bi[k-1] = ti;
            }
        }
    }
}

// ---------------- partitioned kNN: packed f32x2, 2 queries/thread ----------------
// grid: (ceil(half/128), NPART). Thread handles queries i0 and i0+half.
// Tail j's padded via sqs=+inf (never selected: e becomes +inf or NaN).
template<int DIM>
__global__ void __launch_bounds__(128)
knn_part_kernel(const float* __restrict__ X, const float* __restrict__ sq,
                int n, int chunk, int half){
    const int TS = 128;
    const int Q  = DIM/4;
    __shared__ float4 xs[TS*Q];
    __shared__ float  sqs[TS];
    int tid = threadIdx.x;
    int i0 = blockIdx.x*128 + tid;
    int i1 = i0 + half;
    bool vA = (i0 < half);
    bool vB = vA && (i1 < n);
    int p = blockIdx.y;
    int jbeg = p * chunk;
    int jend = min(n, jbeg + chunk);

    const u64* Xp = (const u64*)X;
    int ia = vA ? i0 : 0;
    int ib = vB ? i1 : 0;
    u64 xa[DIM/2], xb[DIM/2];
#pragma unroll
    for (int d = 0; d < DIM/2; d++){
        xa[d] = Xp[(size_t)ia*(DIM/2) + d];
        xb[d] = Xp[(size_t)ib*(DIM/2) + d];
    }
    float bdA[KNN], bdB[KNN]; int biA[KNN], biB[KNN];
#pragma unroll
    for (int k = 0; k < KNN; k++){
        bdA[k] = INFINITY; biA[k] = -1;
        bdB[k] = INFINITY; biB[k] = -1;
    }

    for (int jt = jbeg; jt < jend; jt += TS){
        int tile = min(TS, jend - jt);
        __syncthreads();
        for (int t = tid; t < tile*Q; t += 128)
            xs[t] = reinterpret_cast<const float4*>(X)[jt*Q + t];
        for (int t = tid; t < TS; t += 128)
            sqs[t] = (t < tile) ? sq[jt + t] : INFINITY;
        __syncthreads();
        const ulonglong2* xp = (const ulonglong2*)xs;

#pragma unroll 1
        for (int jj = 0; jj < TS; jj += 4){
            u64 aA0=0, aA1=0, aA2=0, aA3=0;
            u64 aB0=0, aB1=0, aB2=0, aB3=0;
#pragma unroll
            for (int q = 0; q < Q; q++){
                ulonglong2 p0 = xp[(jj+0)*Q + q];
                ulonglong2 p1 = xp[(jj+1)*Q + q];
                ulonglong2 p2 = xp[(jj+2)*Q + q];
                ulonglong2 p3 = xp[(jj+3)*Q + q];
                u64 w0 = xa[2*q], w1 = xa[2*q+1];
                aA0 = f2fma(w0, p0.x, aA0); aA0 = f2fma(w1, p0.y, aA0);
                aA1 = f2fma(w0, p1.x, aA1); aA1 = f2fma(w1, p1.y, aA1);
                aA2 = f2fma(w0, p2.x, aA2); aA2 = f2fma(w1, p2.y, aA2);
                aA3 = f2fma(w0, p3.x, aA3); aA3 = f2fma(w1, p3.y, aA3);
                u64 v0 = xb[2*q], v1 = xb[2*q+1];
                aB0 = f2fma(v0, p0.x, aB0); aB0 = f2fma(v1, p0.y, aB0);
                aB1 = f2fma(v0, p1.x, aB1); aB1 = f2fma(v1, p1.y, aB1);
                aB2 = f2fma(v0, p2.x, aB2); aB2 = f2fma(v1, p2.y, aB2);
                aB3 = f2fma(v0, p3.x, aB3); aB3 = f2fma(v1, p3.y, aB3);
            }
            int j0 = jt + jj;
            float s0 = sqs[jj+0], s1 = sqs[jj+1], s2 = sqs[jj+2], s3 = sqs[jj+3];

            float eA0 = fmaf(-2.f, f2hadd(aA0), s0);
            float eA1 = fmaf(-2.f, f2hadd(aA1), s1);
            float eA2 = fmaf(-2.f, f2hadd(aA2), s2);
            float eA3 = fmaf(-2.f, f2hadd(aA3), s3);
            eA0 = (j0+0 == i0) ? INFINITY : eA0;
            eA1 = (j0+1 == i0) ? INFINITY : eA1;
            eA2 = (j0+2 == i0) ? INFINITY : eA2;
            eA3 = (j0+3 == i0) ? INFINITY : eA3;
            upd6(eA0, j0+0, bdA, biA);
            upd6(eA1, j0+1, bdA, biA);
            upd6(eA2, j0+2, bdA, biA);
            upd6(eA3, j0+3, bdA, biA);

            float eB0 = fmaf(-2.f, f2hadd(aB0), s0);
            float eB1 = fmaf(-2.f, f2hadd(aB1), s1);
            float eB2 = fmaf(-2.f, f2hadd(aB2), s2);
            float eB3 = fmaf(-2.f, f2hadd(aB3), s3);
            eB0 = (j0+0 == i1) ? INFINITY : eB0;
            eB1 = (j0+1 == i1) ? INFINITY : eB1;
            eB2 = (j0+2 == i1) ? INFINITY : eB2;
            eB3 = (j0+3 == i1) ? INFINITY : eB3;
            upd6(eB0, j0+0, bdB, biB);
            upd6(eB1, j0+1, bdB, biB);
            upd6(eB2, j0+2, bdB, biB);
            upd6(eB3, j0+3, bdB, biB);
        }
    }
    if (vA){
        int base = (i0*NPART + p)*KNN;
#pragma unroll
        for (int k = 0; k < KNN; k++){ g_cd[base+k] = bdA[k]; g_ci[base+k] = biA[k]; }
    }
    if (vB){
        int base = (i1*NPART + p)*KNN;
#pragma unroll
        for (int k = 0; k < KNN; k++){ g_cd[base+k] = bdB[k]; g_ci[base+k] = biB[k]; }
    }
}

// ---------------- merge NPART*6 candidates -> global top-6 per node ----------------
__global__ void knn_merge_kernel(int n, int* __restrict__ outidx){
    int i = blockIdx.x*blockDim.x + threadIdx.x;
    if (i >= n) return;
    float bd[KNN]; unsigned bi[KNN];
#pragma unroll
    for (int k = 0; k < KNN; k++){ bd[k] = INFINITY; bi[k] = 0xFFFFFFFFu; }
    int base = i*NPART*KNN;
    for (int c = 0; c < NPART*KNN; c++){
        float d = g_cd[base+c];
        int   jraw = g_ci[base+c];
        if (jraw < 0) continue;
        unsigned j = (unsigned)jraw;
        if (d < bd[KNN-1] || (d == bd[KNN-1] && j < bi[KNN-1])){
            bd[KNN-1] = d; bi[KNN-1] = j;
#pragma unroll
            for (int k = KNN-1; k > 0; k--){
                bool sw = (bd[k] < bd[k-1]) || (bd[k] == bd[k-1] && bi[k] < bi[k-1]);
                if (sw){
                    float td = bd[k]; bd[k] = bd[k-1]; bd[k-1] = td;
                    unsigned ti = bi[k]; bi[k] = bi[k-1]; bi[k-1] = ti;
                }
            }
        }
    }
#pragma unroll
    for (int k = 0; k < KNN; k++) outidx[i*KNN+k] = (int)bi[k];
}

// ---------------- dynamic edge conv ----------------
template<int F>
__global__ void edgeconv_kernel(const float* __restrict__ X, const int* __restrict__ idx,
                                const float* __restrict__ W1, const float* __restrict__ b1,
                                const float* __restrict__ W2, const float* __restrict__ b2,
                                int n, float* __restrict__ Y, float* __restrict__ sqout){
    __shared__ float sW1[2*F*32];
    __shared__ float sb1[32];
    __shared__ float sW2[32*32];
    __shared__ float sb2[32];
    for (int t = threadIdx.x; t < 2*F*32; t += blockDim.x) sW1[t] = W1[t];
    for (int t = threadIdx.x; t < 32*32;  t += blockDim.x) sW2[t] = W2[t];
    if (threadIdx.x < 32){ sb1[threadIdx.x] = b1[threadIdx.x]; sb2[threadIdx.x] = b2[threadIdx.x]; }
    __syncthreads();
    int i = blockIdx.x*blockDim.x + threadIdx.x;
    if (i >= n) return;

    float base[32];
#pragma unroll
    for (int c = 0; c < 32; c++) base[c] = sb1[c];
    for (int d = 0; d < F; d++){
        float v = X[i*F+d];
#pragma unroll
        for (int c = 0; c < 32; c++) base[c] = fmaf(v, sW1[d*32+c], base[c]);
    }
    float acc[32];
#pragma unroll
    for (int c = 0; c < 32; c++) acc[c] = -INFINITY;

    for (int kk = 0; kk < KNN; kk++){
        int j = idx[i*KNN+kk];
        float h[32];
#pragma unroll
        for (int c = 0; c < 32; c++) h[c] = base[c];
        for (int d = 0; d < F; d++){
            float v = X[j*F+d] - X[i*F+d];
#pragma unroll
            for (int c = 0; c < 32; c++) h[c] = fmaf(v, sW1[(F+d)*32+c], h[c]);
        }
#pragma unroll
        for (int c = 0; c < 32; c++) h[c] = fmaxf(h[c], 0.f);
#pragma unroll
        for (int c = 0; c < 32; c++){
            float o = sb2[c];
#pragma unroll
            for (int k = 0; k < 32; k++) o = fmaf(h[k], sW2[k*32+c], o);
            acc[c] = fmaxf(acc[c], o);
        }
    }
    float sqv = 0.f;
#pragma unroll
    for (int c = 0; c < 32; c++){
        float r = fmaxf(acc[c], 0.f);
        Y[i*32+c] = r;
        sqv = fmaf(r, r, sqv);
    }
    if (sqout) sqout[i] = sqv;
}

// ---------------- cat0 = [x1 | y1]; agg2 init = cat0 (self loop) ----------------
__global__ void cat0_kernel(int n){
    int t = blockIdx.x*blockDim.x + threadIdx.x;
    if (t >= n*48) return;
    int i = t / 48, d = t % 48;
    float v = (d < 16) ? g_x1[i*16+d] : g_y1[i*32 + (d-16)];
    g_cat0[t] = v;
    g_agg2[t] = v;
}

__global__ void scatter2_kernel(const int* __restrict__ src, const int* __restrict__ dst, int E){
    int t = blockIdx.x*blockDim.x + threadIdx.x;
    int e = t / 12;
    if (e >= E) return;
    int q = t % 12;
    int s = src[e], d = dst[e];
    float4 v = reinterpret_cast<const float4*>(g_cat0)[s*12 + q];
    float* a = &g_agg2[d*48 + q*4];
    atomicAdd(a+0, v.x); atomicAdd(a+1, v.y); atomicAdd(a+2, v.z); atomicAdd(a+3, v.w);
}

// ---------------- MLP layer 1 ----------------
__global__ void mlp1_kernel(const float* __restrict__ W, const float* __restrict__ b, int n){
    __shared__ float sW[96*96];
    __shared__ float sb[96];
    for (int t = threadIdx.x; t < 96*96; t += blockDim.x) sW[t] = W[t];
    for (int t = threadIdx.x; t < 96;    t += blockDim.x) sb[t] = b[t];
    __syncthreads();
    int i = blockIdx.x*blockDim.x + threadIdx.x;
    if (i >= n) return;
    float acc[96];
#pragma unroll
    for (int c = 0; c < 96; c++) acc[c] = sb[c];
    for (int d = 0; d < 64; d++){
        float v = g_x3[i*64+d];
#pragma unroll
        for (int c = 0; c < 96; c++) acc[c] = fmaf(v, sW[d*96+c], acc[c]);
    }
    for (int d = 0; d < 32; d++){
        float v = g_y2[i*32+d];
#pragma unroll
        for (int c = 0; c < 96; c++) acc[c] = fmaf(v, sW[(64+d)*96+c], acc[c]);
    }
#pragma unroll
    for (int c = 0; c < 96; c++) g_h1[i*96+c] = fmaxf(acc[c], 0.f);
}

// ---------------- MLP layers 2..out ----------------
__global__ void mlp2_kernel(const float* __restrict__ W2, const float* __restrict__ b2,
                            const float* __restrict__ W3, const float* __restrict__ b3,
                            const float* __restrict__ Wo, const float* __restrict__ bo,
                            int n, float* __restrict__ out){
    __shared__ float sW2[96*32]; __shared__ float sb2v[32];
    __shared__ float sW3[32*8];  __shared__ float sb3v[8];
    __shared__ float sWo[8];     __shared__ float sbo;
    for (int t = threadIdx.x; t < 96*32; t += blockDim.x) sW2[t] = W2[t];
    for (int t = threadIdx.x; t < 32*8;  t += blockDim.x) sW3[t] = W3[t];
    if (threadIdx.x < 32) sb2v[threadIdx.x] = b2[threadIdx.x];
    if (threadIdx.x < 8){ sb3v[threadIdx.x] = b3[threadIdx.x]; sWo[threadIdx.x] = Wo[threadIdx.x]; }
    if (threadIdx.x == 0) sbo = bo[0];
    __syncthreads();
    int i = blockIdx.x*blockDim.x + threadIdx.x;
    if (i >= n) return;
    float h[32];
#pragma unroll
    for (int c = 0; c < 32; c++) h[c] = sb2v[c];
    for (int d = 0; d < 96; d++){
        float v = g_h1[i*96+d];
#pragma unroll
        for (int c = 0; c < 32; c++) h[c] = fmaf(v, sW2[d*32+c], h[c]);
    }
#pragma unroll
    for (int c = 0; c < 32; c++) h[c] = fmaxf(h[c], 0.f);
    float g[8];
#pragma unroll
    for (int c = 0; c < 8; c++){
        float o = sb3v[c];
#pragma unroll
        for (int k = 0; k < 32; k++) o = fmaf(h[k], sW3[k*8+c], o);
        g[c] = fmaxf(o, 0.f);
    }
    float z = sbo;
#pragma unroll
    for (int c = 0; c < 8; c++) z = fmaf(g[c], sWo[c], z);
    out[i] = 1.0f / (1.0f + expf(-z));
}

// ---------------- launch ----------------
extern "C" void kernel_launch(void* const* d_in, const int* in_sizes, int n_in,
                              void* d_out, int out_size){
    const float* x   = (const float*)d_in[0];
    const int*   ei  = (const int*)  d_in[1];
    int n = in_sizes[0] / 16;
    int E = in_sizes[1] / 2;
    const int* src = ei;
    const int* dst = ei + E;

    const float* cW1 = (const float*)d_in[2];
    const float* cb1 = (const float*)d_in[5];
    const float* cW3 = (const float*)d_in[6];
    const float* cb3 = (const float*)d_in[9];
    const float* e1W1=(const float*)d_in[10]; const float* e1b1=(const float*)d_in[11];
    const float* e1W2=(const float*)d_in[12]; const float* e1b2=(const float*)d_in[13];
    const float* e2W1=(const float*)d_in[14]; const float* e2b1=(const float*)d_in[15];
    const float* e2W2=(const float*)d_in[16]; const float* e2b2=(const float*)d_in[17];
    const float* l1W =(const float*)d_in[18]; const float* l1b =(const float*)d_in[19];
    const float* l2W =(const float*)d_in[20]; const float* l2b =(const float*)d_in[21];
    const float* l3W =(const float*)d_in[22]; const float* l3b =(const float*)d_in[23];
    const float* oW  =(const float*)d_in[24]; const float* ob  =(const float*)d_in[25];
    float* out = (float*)d_out;

    void *p_agg1, *p_x1, *p_sq1, *p_idx1, *p_y1, *p_sq2, *p_agg2, *p_idx2, *p_x3, *p_y2;
    cudaGetSymbolAddress(&p_agg1, g_agg1);
    cudaGetSymbolAddress(&p_x1,   g_x1);
    cudaGetSymbolAddress(&p_sq1,  g_sq1);
    cudaGetSymbolAddress(&p_idx1, g_idx1);
    cudaGetSymbolAddress(&p_y1,   g_y1);
    cudaGetSymbolAddress(&p_sq2,  g_sq2);
    cudaGetSymbolAddress(&p_agg2, g_agg2);
    cudaGetSymbolAddress(&p_idx2, g_idx2);
    cudaGetSymbolAddress(&p_x3,   g_x3);
    cudaGetSymbolAddress(&p_y2,   g_y2);

    int nb = (n + 127) / 128;
    int half = (n + 1) / 2;
    int nbq = (half + 127) / 128;
    int chunk = (n + NPART - 1) / NPART;
    dim3 knngrid(nbq, NPART);

    // FeaSt 1 (heads=1 => attention == 1 => segment-mean then GEMM)
    init1_kernel<<<(n*16 + 255)/256, 256>>>(x, n);
    scatter1_kernel<<<(E*4 + 255)/256, 256>>>(src, dst, x, E);
    feast_kernel<16,16,true><<<nb,128>>>((const float*)p_agg1, cW1, cb1, n,
                                         (float*)p_x1, (float*)p_sq1);
    // kNN on x1 (dim 16): partitioned + merge
    knn_part_kernel<16><<<knngrid,128>>>((const float*)p_x1, (const float*)p_sq1, n, chunk, half);
    knn_merge_kernel<<<(n+255)/256,256>>>(n, (int*)p_idx1);
    edgeconv_kernel<16><<<nb,128>>>((const float*)p_x1, (const int*)p_idx1,
                                    e1W1, e1b1, e1W2, e1b2, n,
                                    (float*)p_y1, (float*)p_sq2);
    // FeaSt 2 on cat0 = [x1|y1]
    cat0_kernel<<<(n*48 + 255)/256, 256>>>(n);
    scatter2_kernel<<<(E*12 + 255)/256, 256>>>(src, dst, E);
    feast_kernel<48,64,false><<<nb,128>>>((const float*)p_agg2, cW3, cb3, n,
                                          (float*)p_x3, nullptr);
    // kNN on y1 (dim 32): partitioned + merge
    knn_part_kernel<32><<<knngrid,128>>>((const float*)p_y1, (const float*)p_sq2, n, chunk, half);
    knn_merge_kernel<<<(n+255)/256,256>>>(n, (int*)p_idx2);
    edgeconv_kernel<32><<<nb,128>>>((const float*)p_y1, (const int*)p_idx2,
                                    e2W1, e2b1, e2W2, e2b2, n,
                                    (float*)p_y2, nullptr);
    // Final MLP
    mlp1_kernel<<<nb,128>>>(l1W, l1b, n);
    mlp2_kernel<<<nb,128>>>(l2W, l2b, l3W, l3b, oW, ob, n, out);
}